// round 2
// baseline (speedup 1.0000x reference)
#include <cuda_runtime.h>
#include <cuda_bf16.h>

// Problem constants
#define BATCH 2
#define SEQ   2048
#define DMODEL 1024
#define DSTATE 16
#define LC 64            // chunk length
#define NC (SEQ / LC)    // 32 chunks

// Scratch (device globals: no allocation allowed in kernel_launch)
__device__ float g_bt[BATCH * SEQ * DSTATE];                 // B_t projection (b, l, s)
__device__ float g_hstate[BATCH * NC * DMODEL * DSTATE];     // chunk states (b, c, d, s)

// ---------------------------------------------------------------------------
// K1: B_t[b,l,s] = sum_d x[b,l,d] * B_w[s,d]
// One thread per (b*l, s). 65536 threads. float4 inner loop over d.
// ---------------------------------------------------------------------------
__global__ void k1_bproj(const float* __restrict__ x, const float* __restrict__ Bw) {
    int g = blockIdx.x * blockDim.x + threadIdx.x;   // 0 .. BATCH*SEQ*DSTATE-1
    int s  = g & (DSTATE - 1);
    int bl = g >> 4;
    const float4* xr = reinterpret_cast<const float4*>(x + (size_t)bl * DMODEL);
    const float4* bw = reinterpret_cast<const float4*>(Bw + (size_t)s * DMODEL);
    float acc0 = 0.f, acc1 = 0.f, acc2 = 0.f, acc3 = 0.f;
#pragma unroll 8
    for (int i = 0; i < DMODEL / 4; i++) {
        float4 xv = xr[i];
        float4 bv = bw[i];
        acc0 = fmaf(xv.x, bv.x, acc0);
        acc1 = fmaf(xv.y, bv.y, acc1);
        acc2 = fmaf(xv.z, bv.z, acc2);
        acc3 = fmaf(xv.w, bv.w, acc3);
    }
    g_bt[bl * DSTATE + s] = (acc0 + acc1) + (acc2 + acc3);
}

// ---------------------------------------------------------------------------
// K2: local chunk scan. grid=(NC, DMODEL/128, BATCH), block=128.
// Thread owns (b, c, d): 16 states over LC steps starting from 0.
// Writes end-of-chunk local states to g_hstate[b][c][d][s].
// ---------------------------------------------------------------------------
__global__ void k2_localscan(const float* __restrict__ logA) {
    const int c = blockIdx.x;
    const int d = blockIdx.y * blockDim.x + threadIdx.x;
    const int b = blockIdx.z;

    __shared__ float4 bts[LC][DSTATE / 4];   // chunk of B_t, broadcast reads
    {
        const float4* src = reinterpret_cast<const float4*>(
            g_bt + ((size_t)b * SEQ + (size_t)c * LC) * DSTATE);
        for (int i = threadIdx.x; i < LC * (DSTATE / 4); i += blockDim.x)
            bts[i / (DSTATE / 4)][i % (DSTATE / 4)] = src[i];
    }
    __syncthreads();

    float a[DSTATE], h[DSTATE];
#pragma unroll
    for (int s = 0; s < DSTATE; s++) {
        a[s] = expf(-expf(logA[d * DSTATE + s]));
        h[s] = 0.f;
    }

#pragma unroll 4
    for (int l = 0; l < LC; l++) {
#pragma unroll
        for (int j = 0; j < DSTATE / 4; j++) {
            float4 bv = bts[l][j];
            h[4*j+0] = fmaf(a[4*j+0], h[4*j+0], bv.x);
            h[4*j+1] = fmaf(a[4*j+1], h[4*j+1], bv.y);
            h[4*j+2] = fmaf(a[4*j+2], h[4*j+2], bv.z);
            h[4*j+3] = fmaf(a[4*j+3], h[4*j+3], bv.w);
        }
    }

    float4* out = reinterpret_cast<float4*>(
        g_hstate + (((size_t)b * NC + c) * DMODEL + d) * DSTATE);
#pragma unroll
    for (int j = 0; j < DSTATE / 4; j++)
        out[j] = make_float4(h[4*j], h[4*j+1], h[4*j+2], h[4*j+3]);
}

// ---------------------------------------------------------------------------
// K3: cross-chunk combine. One thread per (b,d,s) = 32768 threads.
// In place: g_hstate[b][c][d][s] becomes the ENTRY state for chunk c.
//   H_c = A^LC * H_{c-1} + local_end_c ;  entry(c) = H_{c-1}
// ---------------------------------------------------------------------------
__global__ void k3_combine(const float* __restrict__ logA) {
    int g = blockIdx.x * blockDim.x + threadIdx.x;   // 0 .. B*D*S-1
    int s = g & (DSTATE - 1);
    int d = (g >> 4) & (DMODEL - 1);
    int b = g >> 14;

    float a = expf(-expf(logA[d * DSTATE + s]));
    // a^LC, LC=64 -> 6 squarings
    float aL = a;
    aL = aL * aL; aL = aL * aL; aL = aL * aL;
    aL = aL * aL; aL = aL * aL; aL = aL * aL;

    float H = 0.f;
#pragma unroll
    for (int c = 0; c < NC; c++) {
        size_t off = (((size_t)b * NC + c) * DMODEL + d) * DSTATE + s;
        float e = g_hstate[off];
        g_hstate[off] = H;            // entry state for chunk c
        H = fmaf(aL, H, e);
    }
}

// ---------------------------------------------------------------------------
// K4: final scan + output. grid=(NC, DMODEL/128, BATCH), block=128.
// h initialized to entry state; per step: recur, project with C, add skip.
// Coalesced x loads and y stores (threads = consecutive d).
// ---------------------------------------------------------------------------
__global__ void k4_output(const float* __restrict__ x,
                          const float* __restrict__ logA,
                          const float* __restrict__ Cw,
                          const float* __restrict__ Dv,
                          float* __restrict__ y) {
    const int c = blockIdx.x;
    const int d = blockIdx.y * blockDim.x + threadIdx.x;
    const int b = blockIdx.z;

    __shared__ float4 bts[LC][DSTATE / 4];
    {
        const float4* src = reinterpret_cast<const float4*>(
            g_bt + ((size_t)b * SEQ + (size_t)c * LC) * DSTATE);
        for (int i = threadIdx.x; i < LC * (DSTATE / 4); i += blockDim.x)
            bts[i / (DSTATE / 4)][i % (DSTATE / 4)] = src[i];
    }
    __syncthreads();

    float a[DSTATE], h[DSTATE], cw[DSTATE];
    {
        const float4* hin = reinterpret_cast<const float4*>(
            g_hstate + (((size_t)b * NC + c) * DMODEL + d) * DSTATE);
        const float4* cwp = reinterpret_cast<const float4*>(Cw + (size_t)d * DSTATE);
#pragma unroll
        for (int j = 0; j < DSTATE / 4; j++) {
            float4 hv = hin[j];
            h[4*j] = hv.x; h[4*j+1] = hv.y; h[4*j+2] = hv.z; h[4*j+3] = hv.w;
            float4 cv = cwp[j];
            cw[4*j] = cv.x; cw[4*j+1] = cv.y; cw[4*j+2] = cv.z; cw[4*j+3] = cv.w;
        }
    }
#pragma unroll
    for (int s = 0; s < DSTATE; s++)
        a[s] = expf(-expf(logA[d * DSTATE + s]));
    const float dv = Dv[d];

    const size_t base = ((size_t)b * SEQ + (size_t)c * LC) * DMODEL + d;

#pragma unroll 4
    for (int l = 0; l < LC; l++) {
        float acc = 0.f;
#pragma unroll
        for (int j = 0; j < DSTATE / 4; j++) {
            float4 bv = bts[l][j];
            h[4*j+0] = fmaf(a[4*j+0], h[4*j+0], bv.x);
            h[4*j+1] = fmaf(a[4*j+1], h[4*j+1], bv.y);
            h[4*j+2] = fmaf(a[4*j+2], h[4*j+2], bv.z);
            h[4*j+3] = fmaf(a[4*j+3], h[4*j+3], bv.w);
            acc = fmaf(cw[4*j+0], h[4*j+0], acc);
            acc = fmaf(cw[4*j+1], h[4*j+1], acc);
            acc = fmaf(cw[4*j+2], h[4*j+2], acc);
            acc = fmaf(cw[4*j+3], h[4*j+3], acc);
        }
        size_t off = base + (size_t)l * DMODEL;
        y[off] = fmaf(dv, x[off], acc);
    }
}

// ---------------------------------------------------------------------------
extern "C" void kernel_launch(void* const* d_in, const int* in_sizes, int n_in,
                              void* d_out, int out_size) {
    const float* x    = (const float*)d_in[0];   // (B, L, D)
    const float* logA = (const float*)d_in[1];   // (D, S)
    const float* Bw   = (const float*)d_in[2];   // (S, D)
    const float* Cw   = (const float*)d_in[3];   // (D, S)
    const float* Dv   = (const float*)d_in[4];   // (D,)
    float* y = (float*)d_out;                    // (B, L, D)

    // K1: B_t projection
    {
        int total = BATCH * SEQ * DSTATE;        // 65536
        k1_bproj<<<total / 256, 256>>>(x, Bw);
    }
    // K2: local chunk scans
    {
        dim3 grid(NC, DMODEL / 128, BATCH);
        k2_localscan<<<grid, 128>>>(logA);
    }
    // K3: cross-chunk combine
    {
        int total = BATCH * DMODEL * DSTATE;     // 32768
        k3_combine<<<total / 256, 256>>>(logA);
    }
    // K4: final scan + output
    {
        dim3 grid(NC, DMODEL / 128, BATCH);
        k4_output<<<grid, 128>>>(x, logA, Cw, Dv, y);
    }
}

// round 3
// speedup vs baseline: 2.3746x; 2.3746x over previous
#include <cuda_runtime.h>
#include <cuda_bf16.h>

// Problem constants
#define BATCH 2
#define SEQ   2048
#define DMODEL 1024
#define DSTATE 16
#define LC 32            // chunk length
#define NC (SEQ / LC)    // 64 chunks

// Scratch (device globals: no allocation allowed in kernel_launch)
__device__ float g_bt[BATCH * SEQ * DSTATE];                 // B_t projection (b, l, s)
__device__ float g_hstate[BATCH * NC * DMODEL * DSTATE];     // chunk states (b, c, d, s)
__device__ float g_abar[DMODEL * DSTATE];                    // exp(-exp(logA))
__device__ float g_aL[DMODEL * DSTATE];                      // abar^LC

// ---------------------------------------------------------------------------
// K0: precompute A_bar and A_bar^LC  (16384 threads, trivial)
// ---------------------------------------------------------------------------
__global__ void k0_precompute(const float* __restrict__ logA) {
    int i = blockIdx.x * blockDim.x + threadIdx.x;
    float a = expf(-expf(logA[i]));
    g_abar[i] = a;
    float aL = a;                       // a^32 = 5 squarings
    aL = aL * aL; aL = aL * aL; aL = aL * aL; aL = aL * aL; aL = aL * aL;
    g_aL[i] = aL;
}

// ---------------------------------------------------------------------------
// K1: B_t[b,l,s] = sum_d x[b,l,d] * B_w[s,d]
// One WARP per (b,l) row. Lane ell covers d = 4*ell + 128*it (it=0..7).
// All loads coalesced; Bw (64KB) stays L1-resident. shfl-xor reduction.
// ---------------------------------------------------------------------------
__global__ void k1_bproj(const float* __restrict__ x, const float* __restrict__ Bw) {
    const int warp = (blockIdx.x * blockDim.x + threadIdx.x) >> 5;  // 0..BATCH*SEQ-1
    const int lane = threadIdx.x & 31;

    const float4* xr = reinterpret_cast<const float4*>(x + (size_t)warp * DMODEL) + lane;
    float acc[DSTATE];
#pragma unroll
    for (int s = 0; s < DSTATE; s++) acc[s] = 0.f;

#pragma unroll
    for (int it = 0; it < DMODEL / 128; it++) {
        float4 xv = xr[it * 32];
#pragma unroll
        for (int s = 0; s < DSTATE; s++) {
            const float4 bv = reinterpret_cast<const float4*>(
                Bw + (size_t)s * DMODEL + it * 128)[lane];
            acc[s] = fmaf(xv.x, bv.x, acc[s]);
            acc[s] = fmaf(xv.y, bv.y, acc[s]);
            acc[s] = fmaf(xv.z, bv.z, acc[s]);
            acc[s] = fmaf(xv.w, bv.w, acc[s]);
        }
    }
    // butterfly reduce each of the 16 sums across the warp
#pragma unroll
    for (int s = 0; s < DSTATE; s++) {
        float v = acc[s];
        v += __shfl_xor_sync(0xffffffffu, v, 16);
        v += __shfl_xor_sync(0xffffffffu, v, 8);
        v += __shfl_xor_sync(0xffffffffu, v, 4);
        v += __shfl_xor_sync(0xffffffffu, v, 2);
        v += __shfl_xor_sync(0xffffffffu, v, 1);
        if (lane == s) g_bt[warp * DSTATE + s] = v;
    }
}

// ---------------------------------------------------------------------------
// K2: local chunk scan. grid=(NC, DMODEL/128, BATCH), block=128.
// Thread owns (b, c, d): 16 states over LC steps starting from 0.
// ---------------------------------------------------------------------------
__global__ void k2_localscan() {
    const int c = blockIdx.x;
    const int d = blockIdx.y * blockDim.x + threadIdx.x;
    const int b = blockIdx.z;

    __shared__ float4 bts[LC][DSTATE / 4];   // chunk of B_t, broadcast reads
    {
        const float4* src = reinterpret_cast<const float4*>(
            g_bt + ((size_t)b * SEQ + (size_t)c * LC) * DSTATE);
        for (int i = threadIdx.x; i < LC * (DSTATE / 4); i += blockDim.x)
            bts[i / (DSTATE / 4)][i % (DSTATE / 4)] = src[i];
    }
    __syncthreads();

    float a[DSTATE], h[DSTATE];
    {
        const float4* ap = reinterpret_cast<const float4*>(g_abar + d * DSTATE);
#pragma unroll
        for (int j = 0; j < DSTATE / 4; j++) {
            float4 av = ap[j];
            a[4*j] = av.x; a[4*j+1] = av.y; a[4*j+2] = av.z; a[4*j+3] = av.w;
        }
    }
#pragma unroll
    for (int s = 0; s < DSTATE; s++) h[s] = 0.f;

#pragma unroll 4
    for (int l = 0; l < LC; l++) {
#pragma unroll
        for (int j = 0; j < DSTATE / 4; j++) {
            float4 bv = bts[l][j];
            h[4*j+0] = fmaf(a[4*j+0], h[4*j+0], bv.x);
            h[4*j+1] = fmaf(a[4*j+1], h[4*j+1], bv.y);
            h[4*j+2] = fmaf(a[4*j+2], h[4*j+2], bv.z);
            h[4*j+3] = fmaf(a[4*j+3], h[4*j+3], bv.w);
        }
    }

    float4* out = reinterpret_cast<float4*>(
        g_hstate + (((size_t)b * NC + c) * DMODEL + d) * DSTATE);
#pragma unroll
    for (int j = 0; j < DSTATE / 4; j++)
        out[j] = make_float4(h[4*j], h[4*j+1], h[4*j+2], h[4*j+3]);
}

// ---------------------------------------------------------------------------
// K3: cross-chunk combine. One thread per (b,d,s) = 32768 threads.
// In place: g_hstate[b][c][d][s] becomes the ENTRY state for chunk c.
// ---------------------------------------------------------------------------
__global__ void k3_combine() {
    int g = blockIdx.x * blockDim.x + threadIdx.x;   // 0 .. B*D*S-1
    int ds = g & (DMODEL * DSTATE - 1);
    int b = g >> 14;

    const float aL = g_aL[ds];
    float H = 0.f;
#pragma unroll
    for (int c = 0; c < NC; c++) {
        size_t off = (((size_t)b * NC + c) * DMODEL * DSTATE) + ds;
        float e = g_hstate[off];
        g_hstate[off] = H;            // entry state for chunk c
        H = fmaf(aL, H, e);
    }
}

// ---------------------------------------------------------------------------
// K4: final scan + output. grid=(NC, DMODEL/128, BATCH), block=128.
// ---------------------------------------------------------------------------
__global__ void k4_output(const float* __restrict__ x,
                          const float* __restrict__ Cw,
                          const float* __restrict__ Dv,
                          float* __restrict__ y) {
    const int c = blockIdx.x;
    const int d = blockIdx.y * blockDim.x + threadIdx.x;
    const int b = blockIdx.z;

    __shared__ float4 bts[LC][DSTATE / 4];
    {
        const float4* src = reinterpret_cast<const float4*>(
            g_bt + ((size_t)b * SEQ + (size_t)c * LC) * DSTATE);
        for (int i = threadIdx.x; i < LC * (DSTATE / 4); i += blockDim.x)
            bts[i / (DSTATE / 4)][i % (DSTATE / 4)] = src[i];
    }
    __syncthreads();

    float a[DSTATE], h[DSTATE], cw[DSTATE];
    {
        const float4* hin = reinterpret_cast<const float4*>(
            g_hstate + (((size_t)b * NC + c) * DMODEL + d) * DSTATE);
        const float4* cwp = reinterpret_cast<const float4*>(Cw + (size_t)d * DSTATE);
        const float4* ap  = reinterpret_cast<const float4*>(g_abar + d * DSTATE);
#pragma unroll
        for (int j = 0; j < DSTATE / 4; j++) {
            float4 hv = hin[j];
            h[4*j] = hv.x; h[4*j+1] = hv.y; h[4*j+2] = hv.z; h[4*j+3] = hv.w;
            float4 cv = cwp[j];
            cw[4*j] = cv.x; cw[4*j+1] = cv.y; cw[4*j+2] = cv.z; cw[4*j+3] = cv.w;
            float4 av = ap[j];
            a[4*j] = av.x; a[4*j+1] = av.y; a[4*j+2] = av.z; a[4*j+3] = av.w;
        }
    }
    const float dv = Dv[d];

    const size_t base = ((size_t)b * SEQ + (size_t)c * LC) * DMODEL + d;

#pragma unroll 4
    for (int l = 0; l < LC; l++) {
        float acc0 = 0.f, acc1 = 0.f, acc2 = 0.f, acc3 = 0.f;
#pragma unroll
        for (int j = 0; j < DSTATE / 4; j++) {
            float4 bv = bts[l][j];
            h[4*j+0] = fmaf(a[4*j+0], h[4*j+0], bv.x);
            h[4*j+1] = fmaf(a[4*j+1], h[4*j+1], bv.y);
            h[4*j+2] = fmaf(a[4*j+2], h[4*j+2], bv.z);
            h[4*j+3] = fmaf(a[4*j+3], h[4*j+3], bv.w);
            acc0 = fmaf(cw[4*j+0], h[4*j+0], acc0);
            acc1 = fmaf(cw[4*j+1], h[4*j+1], acc1);
            acc2 = fmaf(cw[4*j+2], h[4*j+2], acc2);
            acc3 = fmaf(cw[4*j+3], h[4*j+3], acc3);
        }
        size_t off = base + (size_t)l * DMODEL;
        y[off] = fmaf(dv, x[off], (acc0 + acc1) + (acc2 + acc3));
    }
}

// ---------------------------------------------------------------------------
extern "C" void kernel_launch(void* const* d_in, const int* in_sizes, int n_in,
                              void* d_out, int out_size) {
    const float* x    = (const float*)d_in[0];   // (B, L, D)
    const float* logA = (const float*)d_in[1];   // (D, S)
    const float* Bw   = (const float*)d_in[2];   // (S, D)
    const float* Cw   = (const float*)d_in[3];   // (D, S)
    const float* Dv   = (const float*)d_in[4];   // (D,)
    float* y = (float*)d_out;                    // (B, L, D)

    // K0: A_bar, A_bar^LC
    k0_precompute<<<(DMODEL * DSTATE) / 256, 256>>>(logA);

    // K1: B_t projection — one warp per (b,l) row
    {
        int warps = BATCH * SEQ;                 // 4096
        k1_bproj<<<warps * 32 / 256, 256>>>(x, Bw);
    }
    // K2: local chunk scans
    {
        dim3 grid(NC, DMODEL / 128, BATCH);
        k2_localscan<<<grid, 128>>>();
    }
    // K3: cross-chunk combine
    {
        int total = BATCH * DMODEL * DSTATE;     // 32768
        k3_combine<<<total / 256, 256>>>();
    }
    // K4: final scan + output
    {
        dim3 grid(NC, DMODEL / 128, BATCH);
        k4_output<<<grid, 128>>>(x, Cw, Dv, y);
    }
}

// round 4
// speedup vs baseline: 2.6427x; 1.1129x over previous
#include <cuda_runtime.h>
#include <cuda_bf16.h>

// Problem constants
#define BATCH 2
#define SEQ   2048
#define DMODEL 1024
#define DSTATE 16
#define LC 32            // chunk length
#define NC (SEQ / LC)    // 64 chunks

typedef unsigned long long ull;

// Scratch (device globals; 16B aligned for vector loads)
__device__ __align__(16) float g_bt[BATCH * SEQ * DSTATE];              // (b,l,s)
__device__ __align__(16) float g_hstate[BATCH * NC * DMODEL * DSTATE];  // chunk-end states
__device__ __align__(16) float g_hentry[BATCH * NC * DMODEL * DSTATE];  // chunk-entry states
__device__ __align__(16) float g_abar[DMODEL * DSTATE];                 // exp(-exp(logA))
__device__ __align__(16) float g_aL[DMODEL * DSTATE];                   // abar^LC

// ---- packed fp32x2 helpers ------------------------------------------------
__device__ __forceinline__ ull fma2(ull a, ull b, ull c) {
    ull d;
    asm("fma.rn.f32x2 %0, %1, %2, %3;" : "=l"(d) : "l"(a), "l"(b), "l"(c));
    return d;
}
__device__ __forceinline__ float2 unpack2(ull v) {
    float2 f;
    asm("mov.b64 {%0, %1}, %2;" : "=f"(f.x), "=f"(f.y) : "l"(v));
    return f;
}

// ---------------------------------------------------------------------------
// K0: precompute A_bar and A_bar^LC
// ---------------------------------------------------------------------------
__global__ void k0_precompute(const float* __restrict__ logA) {
    int i = blockIdx.x * blockDim.x + threadIdx.x;
    float a = expf(-expf(logA[i]));
    g_abar[i] = a;
    float aL = a;                       // a^32 = 5 squarings
    aL = aL * aL; aL = aL * aL; aL = aL * aL; aL = aL * aL; aL = aL * aL;
    g_aL[i] = aL;
}

// ---------------------------------------------------------------------------
// K1: B_t[b,l,s] = sum_d x[b,l,d] * B_w[s,d]
// One warp per TWO (b,l) rows; lane covers d = 4*lane + 128*it.
// Packed f32x2 accumulation over adjacent d.
// ---------------------------------------------------------------------------
__global__ void k1_bproj(const float* __restrict__ x, const float* __restrict__ Bw) {
    const int warp = (blockIdx.x * blockDim.x + threadIdx.x) >> 5;  // 0..BATCH*SEQ/2-1
    const int lane = threadIdx.x & 31;
    const int r0 = warp * 2;

    const ulonglong2* xr0 = reinterpret_cast<const ulonglong2*>(x + (size_t)r0 * DMODEL) + lane;
    const ulonglong2* xr1 = reinterpret_cast<const ulonglong2*>(x + (size_t)(r0 + 1) * DMODEL) + lane;

    ull acc0[DSTATE], acc1[DSTATE];
#pragma unroll
    for (int s = 0; s < DSTATE; s++) { acc0[s] = 0ull; acc1[s] = 0ull; }

#pragma unroll
    for (int it = 0; it < DMODEL / 128; it++) {
        ulonglong2 xa = xr0[it * 32];
        ulonglong2 xb = xr1[it * 32];
#pragma unroll
        for (int s = 0; s < DSTATE; s++) {
            ulonglong2 bv = reinterpret_cast<const ulonglong2*>(
                Bw + (size_t)s * DMODEL + it * 128)[lane];
            acc0[s] = fma2(xa.x, bv.x, acc0[s]);
            acc0[s] = fma2(xa.y, bv.y, acc0[s]);
            acc1[s] = fma2(xb.x, bv.x, acc1[s]);
            acc1[s] = fma2(xb.y, bv.y, acc1[s]);
        }
    }
#pragma unroll
    for (int s = 0; s < DSTATE; s++) {
        float2 p0 = unpack2(acc0[s]);
        float2 p1 = unpack2(acc1[s]);
        float v0 = p0.x + p0.y;
        float v1 = p1.x + p1.y;
        v0 += __shfl_xor_sync(0xffffffffu, v0, 16);
        v0 += __shfl_xor_sync(0xffffffffu, v0, 8);
        v0 += __shfl_xor_sync(0xffffffffu, v0, 4);
        v0 += __shfl_xor_sync(0xffffffffu, v0, 2);
        v0 += __shfl_xor_sync(0xffffffffu, v0, 1);
        v1 += __shfl_xor_sync(0xffffffffu, v1, 16);
        v1 += __shfl_xor_sync(0xffffffffu, v1, 8);
        v1 += __shfl_xor_sync(0xffffffffu, v1, 4);
        v1 += __shfl_xor_sync(0xffffffffu, v1, 2);
        v1 += __shfl_xor_sync(0xffffffffu, v1, 1);
        if (lane == s) {
            g_bt[r0 * DSTATE + s] = v0;
            g_bt[(r0 + 1) * DSTATE + s] = v1;
        }
    }
}

// ---------------------------------------------------------------------------
// K2: local chunk scan (packed). grid=(NC, DMODEL/128, BATCH), block=128.
// ---------------------------------------------------------------------------
__global__ void k2_localscan() {
    const int c = blockIdx.x;
    const int d = blockIdx.y * blockDim.x + threadIdx.x;
    const int b = blockIdx.z;

    __shared__ ulonglong2 bts[LC][4];   // 16 floats = 4 ulonglong2 per step
    {
        const ulonglong2* src = reinterpret_cast<const ulonglong2*>(
            g_bt + ((size_t)b * SEQ + (size_t)c * LC) * DSTATE);
        for (int i = threadIdx.x; i < LC * 4; i += blockDim.x)
            bts[i >> 2][i & 3] = src[i];
    }
    __syncthreads();

    ull a2[8], h2[8];
    {
        const ulonglong2* ap = reinterpret_cast<const ulonglong2*>(g_abar + d * DSTATE);
#pragma unroll
        for (int j = 0; j < 4; j++) {
            ulonglong2 av = ap[j];
            a2[2*j+0] = av.x; a2[2*j+1] = av.y;
        }
    }
#pragma unroll
    for (int k = 0; k < 8; k++) h2[k] = 0ull;

#pragma unroll 4
    for (int l = 0; l < LC; l++) {
#pragma unroll
        for (int j = 0; j < 4; j++) {
            ulonglong2 bv = bts[l][j];
            h2[2*j+0] = fma2(a2[2*j+0], h2[2*j+0], bv.x);
            h2[2*j+1] = fma2(a2[2*j+1], h2[2*j+1], bv.y);
        }
    }

    ulonglong2* out = reinterpret_cast<ulonglong2*>(
        g_hstate + (((size_t)b * NC + c) * DMODEL + d) * DSTATE);
#pragma unroll
    for (int j = 0; j < 4; j++)
        out[j] = make_ulonglong2(h2[2*j], h2[2*j+1]);
}

// ---------------------------------------------------------------------------
// K3: cross-chunk combine. Separate output array => loads front-batched.
// One thread per (b,d,s) = 32768 threads.
// ---------------------------------------------------------------------------
__global__ void k3_combine() {
    int g = blockIdx.x * blockDim.x + threadIdx.x;
    int ds = g & (DMODEL * DSTATE - 1);
    int b = g >> 14;

    const float aL = g_aL[ds];
    const float* __restrict__ src = g_hstate + (size_t)b * NC * DMODEL * DSTATE + ds;
    float* __restrict__ dst = g_hentry + (size_t)b * NC * DMODEL * DSTATE + ds;

    float e[NC];
#pragma unroll
    for (int c = 0; c < NC; c++) e[c] = src[(size_t)c * DMODEL * DSTATE];

    float H = 0.f;
#pragma unroll
    for (int c = 0; c < NC; c++) {
        dst[(size_t)c * DMODEL * DSTATE] = H;
        H = fmaf(aL, H, e[c]);
    }
}

// ---------------------------------------------------------------------------
// K4: final scan + output (packed). grid=(NC, DMODEL/128, BATCH), block=128.
// ---------------------------------------------------------------------------
__global__ void k4_output(const float* __restrict__ x,
                          const float* __restrict__ Cw,
                          const float* __restrict__ Dv,
                          float* __restrict__ y) {
    const int c = blockIdx.x;
    const int d = blockIdx.y * blockDim.x + threadIdx.x;
    const int b = blockIdx.z;

    __shared__ ulonglong2 bts[LC][4];
    {
        const ulonglong2* src = reinterpret_cast<const ulonglong2*>(
            g_bt + ((size_t)b * SEQ + (size_t)c * LC) * DSTATE);
        for (int i = threadIdx.x; i < LC * 4; i += blockDim.x)
            bts[i >> 2][i & 3] = src[i];
    }
    __syncthreads();

    ull a2[8], h2[8], cw2[8];
    {
        const ulonglong2* hin = reinterpret_cast<const ulonglong2*>(
            g_hentry + (((size_t)b * NC + c) * DMODEL + d) * DSTATE);
        const ulonglong2* cwp = reinterpret_cast<const ulonglong2*>(Cw + (size_t)d * DSTATE);
        const ulonglong2* ap  = reinterpret_cast<const ulonglong2*>(g_abar + d * DSTATE);
#pragma unroll
        for (int j = 0; j < 4; j++) {
            ulonglong2 hv = hin[j];  h2[2*j] = hv.x;  h2[2*j+1] = hv.y;
            ulonglong2 cv = cwp[j];  cw2[2*j] = cv.x; cw2[2*j+1] = cv.y;
            ulonglong2 av = ap[j];   a2[2*j] = av.x;  a2[2*j+1] = av.y;
        }
    }
    const float dv = Dv[d];
    const size_t base = ((size_t)b * SEQ + (size_t)c * LC) * DMODEL + d;

#pragma unroll 4
    for (int l = 0; l < LC; l++) {
        ull accA = 0ull, accB = 0ull;
#pragma unroll
        for (int j = 0; j < 4; j++) {
            ulonglong2 bv = bts[l][j];
            h2[2*j+0] = fma2(a2[2*j+0], h2[2*j+0], bv.x);
            h2[2*j+1] = fma2(a2[2*j+1], h2[2*j+1], bv.y);
            accA = fma2(cw2[2*j+0], h2[2*j+0], accA);
            accB = fma2(cw2[2*j+1], h2[2*j+1], accB);
        }
        float2 ua = unpack2(accA);
        float2 ub = unpack2(accB);
        size_t off = base + (size_t)l * DMODEL;
        y[off] = fmaf(dv, x[off], (ua.x + ua.y) + (ub.x + ub.y));
    }
}

// ---------------------------------------------------------------------------
extern "C" void kernel_launch(void* const* d_in, const int* in_sizes, int n_in,
                              void* d_out, int out_size) {
    const float* x    = (const float*)d_in[0];   // (B, L, D)
    const float* logA = (const float*)d_in[1];   // (D, S)
    const float* Bw   = (const float*)d_in[2];   // (S, D)
    const float* Cw   = (const float*)d_in[3];   // (D, S)
    const float* Dv   = (const float*)d_in[4];   // (D,)
    float* y = (float*)d_out;                    // (B, L, D)

    k0_precompute<<<(DMODEL * DSTATE) / 256, 256>>>(logA);

    // K1: one warp per 2 rows -> BATCH*SEQ/2 = 2048 warps
    k1_bproj<<<(BATCH * SEQ / 2) * 32 / 256, 256>>>(x, Bw);

    {
        dim3 grid(NC, DMODEL / 128, BATCH);
        k2_localscan<<<grid, 128>>>();
    }
    k3_combine<<<(BATCH * DMODEL * DSTATE) / 256, 256>>>();
    {
        dim3 grid(NC, DMODEL / 128, BATCH);
        k4_output<<<grid, 128>>>(x, Cw, Dv, y);
    }
}

// round 5
// speedup vs baseline: 2.7866x; 1.0544x over previous
#include <cuda_runtime.h>
#include <cuda_bf16.h>

// Problem constants
#define BATCH 2
#define SEQ   2048
#define DMODEL 1024
#define DSTATE 16
#define LC 32            // chunk length
#define NC (SEQ / LC)    // 64 chunks
#define CG 4             // chunk groups in k3
#define NCG (NC / CG)    // 16 chunks per group

typedef unsigned long long ull;

// Scratch (device globals; 16B aligned for vector loads)
__device__ __align__(16) float g_bt[BATCH * SEQ * DSTATE];              // (b,l,s)
__device__ __align__(16) float g_hstate[BATCH * NC * DMODEL * DSTATE];  // chunk-end states
__device__ __align__(16) float g_hentry[BATCH * NC * DMODEL * DSTATE];  // chunk-entry states
__device__ __align__(16) float g_abar[DMODEL * DSTATE];                 // exp(-exp(logA))
__device__ __align__(16) float g_aL[DMODEL * DSTATE];                   // abar^LC

// ---- packed fp32x2 helpers ------------------------------------------------
__device__ __forceinline__ ull fma2(ull a, ull b, ull c) {
    ull d;
    asm("fma.rn.f32x2 %0, %1, %2, %3;" : "=l"(d) : "l"(a), "l"(b), "l"(c));
    return d;
}
__device__ __forceinline__ float2 unpack2(ull v) {
    float2 f;
    asm("mov.b64 {%0, %1}, %2;" : "=f"(f.x), "=f"(f.y) : "l"(v));
    return f;
}

// ---------------------------------------------------------------------------
// K1: B_t[b,l,s] = sum_d x[b,l,d] * B_w[s,d]   (one warp per TWO rows)
// Blocks >= K1_BLOCKS additionally run the k0 precompute (abar, aL).
// ---------------------------------------------------------------------------
#define K1_BLOCKS ((BATCH * SEQ / 2) * 32 / 256)   // 256
#define K0_BLOCKS ((DMODEL * DSTATE) / 256)        // 64

__global__ void k1_bproj(const float* __restrict__ x, const float* __restrict__ Bw,
                         const float* __restrict__ logA) {
    if (blockIdx.x >= K1_BLOCKS) {
        // k0 role: precompute A_bar and A_bar^LC
        int i = (blockIdx.x - K1_BLOCKS) * blockDim.x + threadIdx.x;
        float a = expf(-expf(logA[i]));
        g_abar[i] = a;
        float aL = a;                   // a^32 = 5 squarings
        aL = aL * aL; aL = aL * aL; aL = aL * aL; aL = aL * aL; aL = aL * aL;
        g_aL[i] = aL;
        return;
    }

    const int warp = (blockIdx.x * blockDim.x + threadIdx.x) >> 5;  // 0..BATCH*SEQ/2-1
    const int lane = threadIdx.x & 31;
    const int r0 = warp * 2;

    const ulonglong2* xr0 = reinterpret_cast<const ulonglong2*>(x + (size_t)r0 * DMODEL) + lane;
    const ulonglong2* xr1 = reinterpret_cast<const ulonglong2*>(x + (size_t)(r0 + 1) * DMODEL) + lane;

    ull acc0[DSTATE], acc1[DSTATE];
#pragma unroll
    for (int s = 0; s < DSTATE; s++) { acc0[s] = 0ull; acc1[s] = 0ull; }

#pragma unroll
    for (int it = 0; it < DMODEL / 128; it++) {
        ulonglong2 xa = xr0[it * 32];
        ulonglong2 xb = xr1[it * 32];
#pragma unroll
        for (int s = 0; s < DSTATE; s++) {
            ulonglong2 bv = reinterpret_cast<const ulonglong2*>(
                Bw + (size_t)s * DMODEL + it * 128)[lane];
            acc0[s] = fma2(xa.x, bv.x, acc0[s]);
            acc0[s] = fma2(xa.y, bv.y, acc0[s]);
            acc1[s] = fma2(xb.x, bv.x, acc1[s]);
            acc1[s] = fma2(xb.y, bv.y, acc1[s]);
        }
    }
#pragma unroll
    for (int s = 0; s < DSTATE; s++) {
        float2 p0 = unpack2(acc0[s]);
        float2 p1 = unpack2(acc1[s]);
        float v0 = p0.x + p0.y;
        float v1 = p1.x + p1.y;
        v0 += __shfl_xor_sync(0xffffffffu, v0, 16);
        v0 += __shfl_xor_sync(0xffffffffu, v0, 8);
        v0 += __shfl_xor_sync(0xffffffffu, v0, 4);
        v0 += __shfl_xor_sync(0xffffffffu, v0, 2);
        v0 += __shfl_xor_sync(0xffffffffu, v0, 1);
        v1 += __shfl_xor_sync(0xffffffffu, v1, 16);
        v1 += __shfl_xor_sync(0xffffffffu, v1, 8);
        v1 += __shfl_xor_sync(0xffffffffu, v1, 4);
        v1 += __shfl_xor_sync(0xffffffffu, v1, 2);
        v1 += __shfl_xor_sync(0xffffffffu, v1, 1);
        if (lane == s) {
            g_bt[r0 * DSTATE + s] = v0;
            g_bt[(r0 + 1) * DSTATE + s] = v1;
        }
    }
}

// ---------------------------------------------------------------------------
// K2: local chunk scan (packed). grid=(NC, DMODEL/128, BATCH), block=128.
// ---------------------------------------------------------------------------
__global__ void k2_localscan() {
    const int c = blockIdx.x;
    const int d = blockIdx.y * blockDim.x + threadIdx.x;
    const int b = blockIdx.z;

    __shared__ ulonglong2 bts[LC][4];   // 16 floats = 4 ulonglong2 per step
    {
        const ulonglong2* src = reinterpret_cast<const ulonglong2*>(
            g_bt + ((size_t)b * SEQ + (size_t)c * LC) * DSTATE);
        for (int i = threadIdx.x; i < LC * 4; i += blockDim.x)
            bts[i >> 2][i & 3] = src[i];
    }
    __syncthreads();

    ull a2[8], h2[8];
    {
        const ulonglong2* ap = reinterpret_cast<const ulonglong2*>(g_abar + d * DSTATE);
#pragma unroll
        for (int j = 0; j < 4; j++) {
            ulonglong2 av = ap[j];
            a2[2*j+0] = av.x; a2[2*j+1] = av.y;
        }
    }
#pragma unroll
    for (int k = 0; k < 8; k++) h2[k] = 0ull;

#pragma unroll 4
    for (int l = 0; l < LC; l++) {
#pragma unroll
        for (int j = 0; j < 4; j++) {
            ulonglong2 bv = bts[l][j];
            h2[2*j+0] = fma2(a2[2*j+0], h2[2*j+0], bv.x);
            h2[2*j+1] = fma2(a2[2*j+1], h2[2*j+1], bv.y);
        }
    }

    ulonglong2* out = reinterpret_cast<ulonglong2*>(
        g_hstate + (((size_t)b * NC + c) * DMODEL + d) * DSTATE);
#pragma unroll
    for (int j = 0; j < 4; j++)
        out[j] = make_ulonglong2(h2[2*j], h2[2*j+1]);
}

// ---------------------------------------------------------------------------
// K3: cross-chunk combine, 2-level. Block = 256 threads = 64 ds x 4 chunk-groups.
// Each thread front-batches 16 chunk-end loads (MLP=16), computes its group-end,
// shares group-ends via smem, then writes its 16 entry states.
// grid = (DMODEL*DSTATE/64, BATCH) = (256, 2) = 512 blocks.
// ---------------------------------------------------------------------------
__global__ void k3_combine() {
    const int ds_local = threadIdx.x & 63;
    const int cg = threadIdx.x >> 6;          // 0..3
    const int ds = blockIdx.x * 64 + ds_local;
    const int b = blockIdx.y;

    const float aL = g_aL[ds];
    float aL16 = aL;                          // aL^NCG, NCG=16 -> 4 squarings
    aL16 = aL16 * aL16; aL16 = aL16 * aL16; aL16 = aL16 * aL16; aL16 = aL16 * aL16;

    const size_t stride = (size_t)DMODEL * DSTATE;
    const float* __restrict__ src =
        g_hstate + (size_t)b * NC * stride + (size_t)cg * NCG * stride + ds;
    float* __restrict__ dst =
        g_hentry + (size_t)b * NC * stride + (size_t)cg * NCG * stride + ds;

    // front-batch the 16 chunk-end loads
    float e[NCG];
#pragma unroll
    for (int k = 0; k < NCG; k++) e[k] = src[(size_t)k * stride];

    // group-local combine (zero-initialized)
    float G = 0.f;
#pragma unroll
    for (int k = 0; k < NCG; k++) G = fmaf(aL, G, e[k]);

    __shared__ float GE[CG][64];
    GE[cg][ds_local] = G;
    __syncthreads();

    // entry state for this group: E = sum_{g<cg} aL16^(cg-1-g) * GE[g]
    float E = 0.f;
#pragma unroll
    for (int g = 0; g < CG - 1; g++)
        if (g < cg) E = fmaf(aL16, E, GE[g][ds_local]);

    // emit entry states for the 16 chunks of this group
    float H = E;
#pragma unroll
    for (int k = 0; k < NCG; k++) {
        dst[(size_t)k * stride] = H;
        H = fmaf(aL, H, e[k]);
    }
}

// ---------------------------------------------------------------------------
// K4: final scan + output (packed). grid=(NC, DMODEL/128, BATCH), block=128.
// ---------------------------------------------------------------------------
__global__ void k4_output(const float* __restrict__ x,
                          const float* __restrict__ Cw,
                          const float* __restrict__ Dv,
                          float* __restrict__ y) {
    const int c = blockIdx.x;
    const int d = blockIdx.y * blockDim.x + threadIdx.x;
    const int b = blockIdx.z;

    __shared__ ulonglong2 bts[LC][4];
    {
        const ulonglong2* src = reinterpret_cast<const ulonglong2*>(
            g_bt + ((size_t)b * SEQ + (size_t)c * LC) * DSTATE);
        for (int i = threadIdx.x; i < LC * 4; i += blockDim.x)
            bts[i >> 2][i & 3] = src[i];
    }
    __syncthreads();

    ull a2[8], h2[8], cw2[8];
    {
        const ulonglong2* hin = reinterpret_cast<const ulonglong2*>(
            g_hentry + (((size_t)b * NC + c) * DMODEL + d) * DSTATE);
        const ulonglong2* cwp = reinterpret_cast<const ulonglong2*>(Cw + (size_t)d * DSTATE);
        const ulonglong2* ap  = reinterpret_cast<const ulonglong2*>(g_abar + d * DSTATE);
#pragma unroll
        for (int j = 0; j < 4; j++) {
            ulonglong2 hv = hin[j];  h2[2*j] = hv.x;  h2[2*j+1] = hv.y;
            ulonglong2 cv = cwp[j];  cw2[2*j] = cv.x; cw2[2*j+1] = cv.y;
            ulonglong2 av = ap[j];   a2[2*j] = av.x;  a2[2*j+1] = av.y;
        }
    }
    const float dv = Dv[d];
    const size_t base = ((size_t)b * SEQ + (size_t)c * LC) * DMODEL + d;

#pragma unroll 4
    for (int l = 0; l < LC; l++) {
        ull accA = 0ull, accB = 0ull;
#pragma unroll
        for (int j = 0; j < 4; j++) {
            ulonglong2 bv = bts[l][j];
            h2[2*j+0] = fma2(a2[2*j+0], h2[2*j+0], bv.x);
            h2[2*j+1] = fma2(a2[2*j+1], h2[2*j+1], bv.y);
            accA = fma2(cw2[2*j+0], h2[2*j+0], accA);
            accB = fma2(cw2[2*j+1], h2[2*j+1], accB);
        }
        float2 ua = unpack2(accA);
        float2 ub = unpack2(accB);
        size_t off = base + (size_t)l * DMODEL;
        y[off] = fmaf(dv, x[off], (ua.x + ua.y) + (ub.x + ub.y));
    }
}

// ---------------------------------------------------------------------------
extern "C" void kernel_launch(void* const* d_in, const int* in_sizes, int n_in,
                              void* d_out, int out_size) {
    const float* x    = (const float*)d_in[0];   // (B, L, D)
    const float* logA = (const float*)d_in[1];   // (D, S)
    const float* Bw   = (const float*)d_in[2];   // (S, D)
    const float* Cw   = (const float*)d_in[3];   // (D, S)
    const float* Dv   = (const float*)d_in[4];   // (D,)
    float* y = (float*)d_out;                    // (B, L, D)

    // K1 (+ fused K0 precompute in trailing blocks)
    k1_bproj<<<K1_BLOCKS + K0_BLOCKS, 256>>>(x, Bw, logA);

    {
        dim3 grid(NC, DMODEL / 128, BATCH);
        k2_localscan<<<grid, 128>>>();
    }
    {
        dim3 grid(DMODEL * DSTATE / 64, BATCH);
        k3_combine<<<grid, 256>>>();
    }
    {
        dim3 grid(NC, DMODEL / 128, BATCH);
        k4_output<<<grid, 128>>>(x, Cw, Dv, y);
    }
}

// round 7
// speedup vs baseline: 2.8323x; 1.0164x over previous
#include <cuda_runtime.h>
#include <cuda_bf16.h>

// Problem constants
#define BATCH 2
#define SEQ   2048
#define DMODEL 1024
#define DSTATE 16
#define LC 32            // chunk length
#define NC (SEQ / LC)    // 64 chunks
#define CG 4             // chunk groups in k3
#define NCG (NC / CG)    // 16 chunks per group

typedef unsigned long long ull;

// Scratch (device globals; 16B aligned for vector loads)
__device__ __align__(16) float g_bt[BATCH * SEQ * DSTATE];              // (b,l,s)
__device__ __align__(16) float g_hstate[BATCH * NC * DMODEL * DSTATE];  // chunk-end states
__device__ __align__(16) float g_hentry[BATCH * NC * DMODEL * DSTATE];  // chunk-entry states
__device__ __align__(16) float g_abar[DMODEL * DSTATE];                 // exp(-exp(logA))
__device__ __align__(16) float g_aL[DMODEL * DSTATE];                   // abar^LC

// ---- packed fp32x2 helpers ------------------------------------------------
__device__ __forceinline__ ull fma2(ull a, ull b, ull c) {
    ull d;
    asm("fma.rn.f32x2 %0, %1, %2, %3;" : "=l"(d) : "l"(a), "l"(b), "l"(c));
    return d;
}
__device__ __forceinline__ float2 unpack2(ull v) {
    float2 f;
    asm("mov.b64 {%0, %1}, %2;" : "=f"(f.x), "=f"(f.y) : "l"(v));
    return f;
}

// ---------------------------------------------------------------------------
// K1: B_t[b,l,s] = sum_d x[b,l,d] * B_w[s,d]   (one warp per TWO rows)
// Blocks >= K1_BLOCKS additionally run the k0 precompute (abar, aL).
// ---------------------------------------------------------------------------
#define K1_BLOCKS ((BATCH * SEQ / 2) * 32 / 256)   // 256
#define K0_BLOCKS ((DMODEL * DSTATE) / 256)        // 64

__global__ void k1_bproj(const float* __restrict__ x, const float* __restrict__ Bw,
                         const float* __restrict__ logA) {
    if (blockIdx.x >= K1_BLOCKS) {
        int i = (blockIdx.x - K1_BLOCKS) * blockDim.x + threadIdx.x;
        float a = expf(-expf(logA[i]));
        g_abar[i] = a;
        float aL = a;                   // a^32 = 5 squarings
        aL = aL * aL; aL = aL * aL; aL = aL * aL; aL = aL * aL; aL = aL * aL;
        g_aL[i] = aL;
        return;
    }

    const int warp = (blockIdx.x * blockDim.x + threadIdx.x) >> 5;  // 0..BATCH*SEQ/2-1
    const int lane = threadIdx.x & 31;
    const int r0 = warp * 2;

    const ulonglong2* xr0 = reinterpret_cast<const ulonglong2*>(x + (size_t)r0 * DMODEL) + lane;
    const ulonglong2* xr1 = reinterpret_cast<const ulonglong2*>(x + (size_t)(r0 + 1) * DMODEL) + lane;

    ull acc0[DSTATE], acc1[DSTATE];
#pragma unroll
    for (int s = 0; s < DSTATE; s++) { acc0[s] = 0ull; acc1[s] = 0ull; }

#pragma unroll
    for (int it = 0; it < DMODEL / 128; it++) {
        ulonglong2 xa = xr0[it * 32];
        ulonglong2 xb = xr1[it * 32];
#pragma unroll
        for (int s = 0; s < DSTATE; s++) {
            ulonglong2 bv = reinterpret_cast<const ulonglong2*>(
                Bw + (size_t)s * DMODEL + it * 128)[lane];
            acc0[s] = fma2(xa.x, bv.x, acc0[s]);
            acc0[s] = fma2(xa.y, bv.y, acc0[s]);
            acc1[s] = fma2(xb.x, bv.x, acc1[s]);
            acc1[s] = fma2(xb.y, bv.y, acc1[s]);
        }
    }
#pragma unroll
    for (int s = 0; s < DSTATE; s++) {
        float2 p0 = unpack2(acc0[s]);
        float2 p1 = unpack2(acc1[s]);
        float v0 = p0.x + p0.y;
        float v1 = p1.x + p1.y;
        v0 += __shfl_xor_sync(0xffffffffu, v0, 16);
        v0 += __shfl_xor_sync(0xffffffffu, v0, 8);
        v0 += __shfl_xor_sync(0xffffffffu, v0, 4);
        v0 += __shfl_xor_sync(0xffffffffu, v0, 2);
        v0 += __shfl_xor_sync(0xffffffffu, v0, 1);
        v1 += __shfl_xor_sync(0xffffffffu, v1, 16);
        v1 += __shfl_xor_sync(0xffffffffu, v1, 8);
        v1 += __shfl_xor_sync(0xffffffffu, v1, 4);
        v1 += __shfl_xor_sync(0xffffffffu, v1, 2);
        v1 += __shfl_xor_sync(0xffffffffu, v1, 1);
        if (lane == s) {
            g_bt[r0 * DSTATE + s] = v0;
            g_bt[(r0 + 1) * DSTATE + s] = v1;
        }
    }
}

// ---------------------------------------------------------------------------
// K2: local chunk scan (packed). grid=(NC, DMODEL/128, BATCH), block=128.
// ---------------------------------------------------------------------------
__global__ void k2_localscan() {
    const int c = blockIdx.x;
    const int d = blockIdx.y * blockDim.x + threadIdx.x;
    const int b = blockIdx.z;

    __shared__ ulonglong2 bts[LC][4];   // 16 floats = 4 ulonglong2 per step
    {
        const ulonglong2* src = reinterpret_cast<const ulonglong2*>(
            g_bt + ((size_t)b * SEQ + (size_t)c * LC) * DSTATE);
        for (int i = threadIdx.x; i < LC * 4; i += blockDim.x)
            bts[i >> 2][i & 3] = src[i];
    }
    __syncthreads();

    ull a2[8], h2[8];
    {
        const ulonglong2* ap = reinterpret_cast<const ulonglong2*>(g_abar + d * DSTATE);
#pragma unroll
        for (int j = 0; j < 4; j++) {
            ulonglong2 av = ap[j];
            a2[2*j+0] = av.x; a2[2*j+1] = av.y;
        }
    }
#pragma unroll
    for (int k = 0; k < 8; k++) h2[k] = 0ull;

#pragma unroll 4
    for (int l = 0; l < LC; l++) {
#pragma unroll
        for (int j = 0; j < 4; j++) {
            ulonglong2 bv = bts[l][j];
            h2[2*j+0] = fma2(a2[2*j+0], h2[2*j+0], bv.x);
            h2[2*j+1] = fma2(a2[2*j+1], h2[2*j+1], bv.y);
        }
    }

    ulonglong2* out = reinterpret_cast<ulonglong2*>(
        g_hstate + (((size_t)b * NC + c) * DMODEL + d) * DSTATE);
#pragma unroll
    for (int j = 0; j < 4; j++)
        out[j] = make_ulonglong2(h2[2*j], h2[2*j+1]);
}

// ---------------------------------------------------------------------------
// K3: cross-chunk combine, 2-level. Block = 256 = 64 ds x 4 chunk-groups.
// ---------------------------------------------------------------------------
__global__ void k3_combine() {
    const int ds_local = threadIdx.x & 63;
    const int cg = threadIdx.x >> 6;          // 0..3
    const int ds = blockIdx.x * 64 + ds_local;
    const int b = blockIdx.y;

    const float aL = g_aL[ds];
    float aL16 = aL;                          // aL^NCG, NCG=16 -> 4 squarings
    aL16 = aL16 * aL16; aL16 = aL16 * aL16; aL16 = aL16 * aL16; aL16 = aL16 * aL16;

    const size_t stride = (size_t)DMODEL * DSTATE;
    const float* __restrict__ src =
        g_hstate + (size_t)b * NC * stride + (size_t)cg * NCG * stride + ds;
    float* __restrict__ dst =
        g_hentry + (size_t)b * NC * stride + (size_t)cg * NCG * stride + ds;

    float e[NCG];
#pragma unroll
    for (int k = 0; k < NCG; k++) e[k] = src[(size_t)k * stride];

    float G = 0.f;
#pragma unroll
    for (int k = 0; k < NCG; k++) G = fmaf(aL, G, e[k]);

    __shared__ float GE[CG][64];
    GE[cg][ds_local] = G;
    __syncthreads();

    float E = 0.f;
#pragma unroll
    for (int g = 0; g < CG - 1; g++)
        if (g < cg) E = fmaf(aL16, E, GE[g][ds_local]);

    float H = E;
#pragma unroll
    for (int k = 0; k < NCG; k++) {
        dst[(size_t)k * stride] = H;
        H = fmaf(aL, H, e[k]);
    }
}

// ---------------------------------------------------------------------------
// K4: final scan + output (packed). grid=(NC, DMODEL/128, BATCH), block=128.
// x values for the whole chunk front-batched into registers (MLP=32).
// ---------------------------------------------------------------------------
__global__ void __launch_bounds__(128)
k4_output(const float* __restrict__ x,
          const float* __restrict__ Cw,
          const float* __restrict__ Dv,
          float* __restrict__ y) {
    const int c = blockIdx.x;
    const int d = blockIdx.y * blockDim.x + threadIdx.x;
    const int b = blockIdx.z;

    const size_t base = ((size_t)b * SEQ + (size_t)c * LC) * DMODEL + d;

    // front-batch all LC x-loads for this chunk (independent, MLP=LC)
    float xv[LC];
#pragma unroll
    for (int l = 0; l < LC; l++) xv[l] = x[base + (size_t)l * DMODEL];

    __shared__ ulonglong2 bts[LC][4];
    {
        const ulonglong2* src = reinterpret_cast<const ulonglong2*>(
            g_bt + ((size_t)b * SEQ + (size_t)c * LC) * DSTATE);
        for (int i = threadIdx.x; i < LC * 4; i += blockDim.x)
            bts[i >> 2][i & 3] = src[i];
    }
    __syncthreads();

    ull a2[8], h2[8], cw2[8];
    {
        const ulonglong2* hin = reinterpret_cast<const ulonglong2*>(
            g_hentry + (((size_t)b * NC + c) * DMODEL + d) * DSTATE);
        const ulonglong2* cwp = reinterpret_cast<const ulonglong2*>(Cw + (size_t)d * DSTATE);
        const ulonglong2* ap  = reinterpret_cast<const ulonglong2*>(g_abar + d * DSTATE);
#pragma unroll
        for (int j = 0; j < 4; j++) {
            ulonglong2 hv = hin[j];  h2[2*j] = hv.x;  h2[2*j+1] = hv.y;
            ulonglong2 cv = cwp[j];  cw2[2*j] = cv.x; cw2[2*j+1] = cv.y;
            ulonglong2 av = ap[j];   a2[2*j] = av.x;  a2[2*j+1] = av.y;
        }
    }
    const float dv = Dv[d];

#pragma unroll
    for (int l = 0; l < LC; l++) {
        ull accA = 0ull, accB = 0ull;
#pragma unroll
        for (int j = 0; j < 4; j++) {
            ulonglong2 bv = bts[l][j];
            h2[2*j+0] = fma2(a2[2*j+0], h2[2*j+0], bv.x);
            h2[2*j+1] = fma2(a2[2*j+1], h2[2*j+1], bv.y);
            accA = fma2(cw2[2*j+0], h2[2*j+0], accA);
            accB = fma2(cw2[2*j+1], h2[2*j+1], accB);
        }
        float2 ua = unpack2(accA);
        float2 ub = unpack2(accB);
        y[base + (size_t)l * DMODEL] = fmaf(dv, xv[l], (ua.x + ua.y) + (ub.x + ub.y));
    }
}

// ---------------------------------------------------------------------------
extern "C" void kernel_launch(void* const* d_in, const int* in_sizes, int n_in,
                              void* d_out, int out_size) {
    const float* x    = (const float*)d_in[0];   // (B, L, D)
    const float* logA = (const float*)d_in[1];   // (D, S)
    const float* Bw   = (const float*)d_in[2];   // (S, D)
    const float* Cw   = (const float*)d_in[3];   // (D, S)
    const float* Dv   = (const float*)d_in[4];   // (D,)
    float* y = (float*)d_out;                    // (B, L, D)

    // K1 (+ fused K0 precompute in trailing blocks)
    k1_bproj<<<K1_BLOCKS + K0_BLOCKS, 256>>>(x, Bw, logA);

    {
        dim3 grid(NC, DMODEL / 128, BATCH);
        k2_localscan<<<grid, 128>>>();
    }
    {
        dim3 grid(DMODEL * DSTATE / 64, BATCH);
        k3_combine<<<grid, 256>>>();
    }
    {
        dim3 grid(NC, DMODEL / 128, BATCH);
        k4_output<<<grid, 128>>>(x, Cw, Dv, y);
    }
}

// round 10
// speedup vs baseline: 2.9311x; 1.0349x over previous
#include <cuda_runtime.h>
#include <cuda_bf16.h>
#include <cstdint>

// Problem constants
#define BATCH 2
#define SEQ   2048
#define DMODEL 1024
#define DSTATE 16
#define LC 32            // chunk length
#define NC (SEQ / LC)    // 64 chunks
#define CG 4             // chunk groups in k3
#define NCG (NC / CG)    // 16 chunks per group

typedef unsigned long long ull;

// Scratch (device globals; 16B aligned for vector loads)
__device__ __align__(16) float g_bt[BATCH * SEQ * DSTATE];              // (b,l,s)
__device__ __align__(16) float g_hstate[BATCH * NC * DMODEL * DSTATE];  // chunk-end states
__device__ __align__(16) float g_hentry[BATCH * NC * DMODEL * DSTATE];  // chunk-entry states
__device__ __align__(16) float g_abar[DMODEL * DSTATE];                 // exp(-exp(logA))
__device__ __align__(16) float g_aL[DMODEL * DSTATE];                   // abar^LC

// ---- packed fp32x2 helpers ------------------------------------------------
__device__ __forceinline__ ull fma2(ull a, ull b, ull c) {
    ull d;
    asm("fma.rn.f32x2 %0, %1, %2, %3;" : "=l"(d) : "l"(a), "l"(b), "l"(c));
    return d;
}
__device__ __forceinline__ float2 unpack2(ull v) {
    float2 f;
    asm("mov.b64 {%0, %1}, %2;" : "=f"(f.x), "=f"(f.y) : "l"(v));
    return f;
}
// ---- cp.async helpers ------------------------------------------------------
__device__ __forceinline__ void cp_async16(unsigned int smem_addr, const void* gptr) {
    asm volatile("cp.async.cg.shared.global [%0], [%1], 16;" :: "r"(smem_addr), "l"(gptr));
}
__device__ __forceinline__ void cp_async_commit() {
    asm volatile("cp.async.commit_group;");
}
__device__ __forceinline__ void cp_async_wait0() {
    asm volatile("cp.async.wait_group 0;" ::: "memory");
}

// ---------------------------------------------------------------------------
// K1: B_t[b,l,s] = sum_d x[b,l,d] * B_w[s,d]   (one warp per TWO rows)
// Blocks >= K1_BLOCKS additionally run the k0 precompute (abar, aL).
// ---------------------------------------------------------------------------
#define K1_BLOCKS ((BATCH * SEQ / 2) * 32 / 256)   // 256
#define K0_BLOCKS ((DMODEL * DSTATE) / 256)        // 64

__global__ void k1_bproj(const float* __restrict__ x, const float* __restrict__ Bw,
                         const float* __restrict__ logA) {
    if (blockIdx.x >= K1_BLOCKS) {
        int i = (blockIdx.x - K1_BLOCKS) * blockDim.x + threadIdx.x;
        float a = expf(-expf(logA[i]));
        g_abar[i] = a;
        float aL = a;                   // a^32 = 5 squarings
        aL = aL * aL; aL = aL * aL; aL = aL * aL; aL = aL * aL; aL = aL * aL;
        g_aL[i] = aL;
        return;
    }

    const int warp = (blockIdx.x * blockDim.x + threadIdx.x) >> 5;  // 0..BATCH*SEQ/2-1
    const int lane = threadIdx.x & 31;
    const int r0 = warp * 2;

    const ulonglong2* xr0 = reinterpret_cast<const ulonglong2*>(x + (size_t)r0 * DMODEL) + lane;
    const ulonglong2* xr1 = reinterpret_cast<const ulonglong2*>(x + (size_t)(r0 + 1) * DMODEL) + lane;

    ull acc0[DSTATE], acc1[DSTATE];
#pragma unroll
    for (int s = 0; s < DSTATE; s++) { acc0[s] = 0ull; acc1[s] = 0ull; }

#pragma unroll
    for (int it = 0; it < DMODEL / 128; it++) {
        ulonglong2 xa = xr0[it * 32];
        ulonglong2 xb = xr1[it * 32];
#pragma unroll
        for (int s = 0; s < DSTATE; s++) {
            ulonglong2 bv = reinterpret_cast<const ulonglong2*>(
                Bw + (size_t)s * DMODEL + it * 128)[lane];
            acc0[s] = fma2(xa.x, bv.x, acc0[s]);
            acc0[s] = fma2(xa.y, bv.y, acc0[s]);
            acc1[s] = fma2(xb.x, bv.x, acc1[s]);
            acc1[s] = fma2(xb.y, bv.y, acc1[s]);
        }
    }
#pragma unroll
    for (int s = 0; s < DSTATE; s++) {
        float2 p0 = unpack2(acc0[s]);
        float2 p1 = unpack2(acc1[s]);
        float v0 = p0.x + p0.y;
        float v1 = p1.x + p1.y;
        v0 += __shfl_xor_sync(0xffffffffu, v0, 16);
        v0 += __shfl_xor_sync(0xffffffffu, v0, 8);
        v0 += __shfl_xor_sync(0xffffffffu, v0, 4);
        v0 += __shfl_xor_sync(0xffffffffu, v0, 2);
        v0 += __shfl_xor_sync(0xffffffffu, v0, 1);
        v1 += __shfl_xor_sync(0xffffffffu, v1, 16);
        v1 += __shfl_xor_sync(0xffffffffu, v1, 8);
        v1 += __shfl_xor_sync(0xffffffffu, v1, 4);
        v1 += __shfl_xor_sync(0xffffffffu, v1, 2);
        v1 += __shfl_xor_sync(0xffffffffu, v1, 1);
        if (lane == s) {
            g_bt[r0 * DSTATE + s] = v0;
            g_bt[(r0 + 1) * DSTATE + s] = v1;
        }
    }
}

// ---------------------------------------------------------------------------
// K2: local chunk scan (packed). grid=(NC, DMODEL/128, BATCH), block=128.
// ---------------------------------------------------------------------------
__global__ void k2_localscan() {
    const int c = blockIdx.x;
    const int d = blockIdx.y * blockDim.x + threadIdx.x;
    const int b = blockIdx.z;

    __shared__ ulonglong2 bts[LC][4];   // 16 floats = 4 ulonglong2 per step
    {
        const ulonglong2* src = reinterpret_cast<const ulonglong2*>(
            g_bt + ((size_t)b * SEQ + (size_t)c * LC) * DSTATE);
        for (int i = threadIdx.x; i < LC * 4; i += blockDim.x)
            bts[i >> 2][i & 3] = src[i];
    }
    __syncthreads();

    ull a2[8], h2[8];
    {
        const ulonglong2* ap = reinterpret_cast<const ulonglong2*>(g_abar + d * DSTATE);
#pragma unroll
        for (int j = 0; j < 4; j++) {
            ulonglong2 av = ap[j];
            a2[2*j+0] = av.x; a2[2*j+1] = av.y;
        }
    }
#pragma unroll
    for (int k = 0; k < 8; k++) h2[k] = 0ull;

#pragma unroll 4
    for (int l = 0; l < LC; l++) {
#pragma unroll
        for (int j = 0; j < 4; j++) {
            ulonglong2 bv = bts[l][j];
            h2[2*j+0] = fma2(a2[2*j+0], h2[2*j+0], bv.x);
            h2[2*j+1] = fma2(a2[2*j+1], h2[2*j+1], bv.y);
        }
    }

    ulonglong2* out = reinterpret_cast<ulonglong2*>(
        g_hstate + (((size_t)b * NC + c) * DMODEL + d) * DSTATE);
#pragma unroll
    for (int j = 0; j < 4; j++)
        out[j] = make_ulonglong2(h2[2*j], h2[2*j+1]);
}

// ---------------------------------------------------------------------------
// K3: cross-chunk combine, 2-level. Block = 256 = 64 ds x 4 chunk-groups.
// ---------------------------------------------------------------------------
__global__ void k3_combine() {
    const int ds_local = threadIdx.x & 63;
    const int cg = threadIdx.x >> 6;          // 0..3
    const int ds = blockIdx.x * 64 + ds_local;
    const int b = blockIdx.y;

    const float aL = g_aL[ds];
    float aL16 = aL;                          // aL^NCG, NCG=16 -> 4 squarings
    aL16 = aL16 * aL16; aL16 = aL16 * aL16; aL16 = aL16 * aL16; aL16 = aL16 * aL16;

    const size_t stride = (size_t)DMODEL * DSTATE;
    const float* __restrict__ src =
        g_hstate + (size_t)b * NC * stride + (size_t)cg * NCG * stride + ds;
    float* __restrict__ dst =
        g_hentry + (size_t)b * NC * stride + (size_t)cg * NCG * stride + ds;

    float e[NCG];
#pragma unroll
    for (int k = 0; k < NCG; k++) e[k] = src[(size_t)k * stride];

    float G = 0.f;
#pragma unroll
    for (int k = 0; k < NCG; k++) G = fmaf(aL, G, e[k]);

    __shared__ float GE[CG][64];
    GE[cg][ds_local] = G;
    __syncthreads();

    float E = 0.f;
#pragma unroll
    for (int g = 0; g < CG - 1; g++)
        if (g < cg) E = fmaf(aL16, E, GE[g][ds_local]);

    float H = E;
#pragma unroll
    for (int k = 0; k < NCG; k++) {
        dst[(size_t)k * stride] = H;
        H = fmaf(aL, H, e[k]);
    }
}

// ---------------------------------------------------------------------------
// K4: final scan + output. grid=(NC, DMODEL/128, BATCH), block=128.
// x tile (32x128 = 16KB) and B_t tile (2KB) staged via cp.async:
// zero register cost, deep MLP, regs ~70 -> high occupancy.
// ---------------------------------------------------------------------------
__global__ void __launch_bounds__(128)
k4_output(const float* __restrict__ x,
          const float* __restrict__ Cw,
          const float* __restrict__ Dv,
          float* __restrict__ y) {
    const int c = blockIdx.x;
    const int d = blockIdx.y * blockDim.x + threadIdx.x;
    const int b = blockIdx.z;

    __shared__ float sx[LC * 128];       // x tile: [l][d_local], 16KB
    __shared__ ulonglong2 bts[LC][4];    // B_t tile: 2KB

    const size_t base = ((size_t)b * SEQ + (size_t)c * LC) * DMODEL + blockIdx.y * 128;

    // async-stage x tile: 1024 float4 = 8 per thread
    {
        unsigned int sx_addr = (unsigned int)__cvta_generic_to_shared(sx);
        const float* xg = x + base;
#pragma unroll
        for (int k = 0; k < 8; k++) {
            int i = threadIdx.x + 128 * k;       // float4 index
            int l = i >> 5;                      // row
            int d4 = i & 31;                     // float4 within row
            cp_async16(sx_addr + i * 16, xg + (size_t)l * DMODEL + d4 * 4);
        }
    }
    // async-stage B_t tile: 128 float4 = 1 per thread
    {
        unsigned int bt_addr = (unsigned int)__cvta_generic_to_shared(&bts[0][0]);
        const float* btg = g_bt + ((size_t)b * SEQ + (size_t)c * LC) * DSTATE;
        cp_async16(bt_addr + threadIdx.x * 16, btg + threadIdx.x * 4);
    }
    cp_async_commit();

    // overlap: per-thread register loads while async copies fly
    ull a2[8], h2[8], cw2[8];
    {
        const ulonglong2* hin = reinterpret_cast<const ulonglong2*>(
            g_hentry + (((size_t)b * NC + c) * DMODEL + d) * DSTATE);
        const ulonglong2* cwp = reinterpret_cast<const ulonglong2*>(Cw + (size_t)d * DSTATE);
        const ulonglong2* ap  = reinterpret_cast<const ulonglong2*>(g_abar + d * DSTATE);
#pragma unroll
        for (int j = 0; j < 4; j++) {
            ulonglong2 hv = hin[j];  h2[2*j] = hv.x;  h2[2*j+1] = hv.y;
            ulonglong2 cv = cwp[j];  cw2[2*j] = cv.x; cw2[2*j+1] = cv.y;
            ulonglong2 av = ap[j];   a2[2*j] = av.x;  a2[2*j+1] = av.y;
        }
    }
    const float dv = Dv[d];

    cp_async_wait0();
    __syncthreads();

    const size_t ybase = base + threadIdx.x;

#pragma unroll 8
    for (int l = 0; l < LC; l++) {
        ull accA = 0ull, accB = 0ull;
#pragma unroll
        for (int j = 0; j < 4; j++) {
            ulonglong2 bv = bts[l][j];
            h2[2*j+0] = fma2(a2[2*j+0], h2[2*j+0], bv.x);
            h2[2*j+1] = fma2(a2[2*j+1], h2[2*j+1], bv.y);
            accA = fma2(cw2[2*j+0], h2[2*j+0], accA);
            accB = fma2(cw2[2*j+1], h2[2*j+1], accB);
        }
        float2 ua = unpack2(accA);
        float2 ub = unpack2(accB);
        float xval = sx[l * 128 + threadIdx.x];
        y[ybase + (size_t)l * DMODEL] = fmaf(dv, xval, (ua.x + ua.y) + (ub.x + ub.y));
    }
}

// ---------------------------------------------------------------------------
extern "C" void kernel_launch(void* const* d_in, const int* in_sizes, int n_in,
                              void* d_out, int out_size) {
    const float* x    = (const float*)d_in[0];   // (B, L, D)
    const float* logA = (const float*)d_in[1];   // (D, S)
    const float* Bw   = (const float*)d_in[2];   // (S, D)
    const float* Cw   = (const float*)d_in[3];   // (D, S)
    const float* Dv   = (const float*)d_in[4];   // (D,)
    float* y = (float*)d_out;                    // (B, L, D)

    // K1 (+ fused K0 precompute in trailing blocks)
    k1_bproj<<<K1_BLOCKS + K0_BLOCKS, 256>>>(x, Bw, logA);

    {
        dim3 grid(NC, DMODEL / 128, BATCH);
        k2_localscan<<<grid, 128>>>();
    }
    {
        dim3 grid(DMODEL * DSTATE / 64, BATCH);
        k3_combine<<<grid, 256>>>();
    }
    {
        dim3 grid(NC, DMODEL / 128, BATCH);
        k4_output<<<grid, 128>>>(x, Cw, Dv, y);
    }
}

// round 16
// speedup vs baseline: 2.9683x; 1.0127x over previous
#include <cuda_runtime.h>
#include <cuda_bf16.h>
#include <cstdint>

// Problem constants
#define BATCH 2
#define SEQ   2048
#define DMODEL 1024
#define DSTATE 16
#define LC 32            // chunk length
#define NC (SEQ / LC)    // 64 chunks
#define CG 4             // chunk groups in k3
#define NCG (NC / CG)    // 16 chunks per group

typedef unsigned long long ull;

// Scratch (device globals; 16B aligned for vector loads)
__device__ __align__(16) float g_bt[BATCH * SEQ * DSTATE];              // (b,l,s)
__device__ __align__(16) float g_hstate[BATCH * NC * DMODEL * DSTATE];  // chunk-end states
__device__ __align__(16) float g_hentry[BATCH * NC * DMODEL * DSTATE];  // chunk-entry states
__device__ __align__(16) float g_abar[DMODEL * DSTATE];                 // exp(-exp(logA))
__device__ __align__(16) float g_aL[DMODEL * DSTATE];                   // abar^LC

// ---- packed fp32x2 helpers ------------------------------------------------
__device__ __forceinline__ ull fma2(ull a, ull b, ull c) {
    ull d;
    asm("fma.rn.f32x2 %0, %1, %2, %3;" : "=l"(d) : "l"(a), "l"(b), "l"(c));
    return d;
}
__device__ __forceinline__ float2 unpack2(ull v) {
    float2 f;
    asm("mov.b64 {%0, %1}, %2;" : "=f"(f.x), "=f"(f.y) : "l"(v));
    return f;
}
// ---- cp.async helpers ------------------------------------------------------
__device__ __forceinline__ void cp_async16(unsigned int smem_addr, const void* gptr) {
    asm volatile("cp.async.cg.shared.global [%0], [%1], 16;" :: "r"(smem_addr), "l"(gptr));
}
__device__ __forceinline__ void cp_async_commit() {
    asm volatile("cp.async.commit_group;");
}
__device__ __forceinline__ void cp_async_wait0() {
    asm volatile("cp.async.wait_group 0;" ::: "memory");
}

// ---------------------------------------------------------------------------
// K1: B_t[b,l,s] = sum_d x[b,l,d] * B_w[s,d]   (one warp per TWO rows)
// Blocks >= K1_BLOCKS additionally run the k0 precompute (abar, aL).
// ---------------------------------------------------------------------------
#define K1_BLOCKS ((BATCH * SEQ / 2) * 32 / 256)   // 256
#define K0_BLOCKS ((DMODEL * DSTATE) / 256)        // 64

__global__ void k1_bproj(const float* __restrict__ x, const float* __restrict__ Bw,
                         const float* __restrict__ logA) {
    if (blockIdx.x >= K1_BLOCKS) {
        int i = (blockIdx.x - K1_BLOCKS) * blockDim.x + threadIdx.x;
        float a = expf(-expf(logA[i]));
        g_abar[i] = a;
        float aL = a;                   // a^32 = 5 squarings
        aL = aL * aL; aL = aL * aL; aL = aL * aL; aL = aL * aL; aL = aL * aL;
        g_aL[i] = aL;
        return;
    }

    const int warp = (blockIdx.x * blockDim.x + threadIdx.x) >> 5;  // 0..BATCH*SEQ/2-1
    const int lane = threadIdx.x & 31;
    const int r0 = warp * 2;

    const ulonglong2* xr0 = reinterpret_cast<const ulonglong2*>(x + (size_t)r0 * DMODEL) + lane;
    const ulonglong2* xr1 = reinterpret_cast<const ulonglong2*>(x + (size_t)(r0 + 1) * DMODEL) + lane;

    ull acc0[DSTATE], acc1[DSTATE];
#pragma unroll
    for (int s = 0; s < DSTATE; s++) { acc0[s] = 0ull; acc1[s] = 0ull; }

#pragma unroll
    for (int it = 0; it < DMODEL / 128; it++) {
        ulonglong2 xa = xr0[it * 32];
        ulonglong2 xb = xr1[it * 32];
#pragma unroll
        for (int s = 0; s < DSTATE; s++) {
            ulonglong2 bv = reinterpret_cast<const ulonglong2*>(
                Bw + (size_t)s * DMODEL + it * 128)[lane];
            acc0[s] = fma2(xa.x, bv.x, acc0[s]);
            acc0[s] = fma2(xa.y, bv.y, acc0[s]);
            acc1[s] = fma2(xb.x, bv.x, acc1[s]);
            acc1[s] = fma2(xb.y, bv.y, acc1[s]);
        }
    }
#pragma unroll
    for (int s = 0; s < DSTATE; s++) {
        float2 p0 = unpack2(acc0[s]);
        float2 p1 = unpack2(acc1[s]);
        float v0 = p0.x + p0.y;
        float v1 = p1.x + p1.y;
        v0 += __shfl_xor_sync(0xffffffffu, v0, 16);
        v0 += __shfl_xor_sync(0xffffffffu, v0, 8);
        v0 += __shfl_xor_sync(0xffffffffu, v0, 4);
        v0 += __shfl_xor_sync(0xffffffffu, v0, 2);
        v0 += __shfl_xor_sync(0xffffffffu, v0, 1);
        v1 += __shfl_xor_sync(0xffffffffu, v1, 16);
        v1 += __shfl_xor_sync(0xffffffffu, v1, 8);
        v1 += __shfl_xor_sync(0xffffffffu, v1, 4);
        v1 += __shfl_xor_sync(0xffffffffu, v1, 2);
        v1 += __shfl_xor_sync(0xffffffffu, v1, 1);
        if (lane == s) {
            g_bt[r0 * DSTATE + s] = v0;
            g_bt[(r0 + 1) * DSTATE + s] = v1;
        }
    }
}

// ---------------------------------------------------------------------------
// K2: local chunk scan (packed). grid=(NC, DMODEL/128, BATCH), block=128.
// ---------------------------------------------------------------------------
__global__ void k2_localscan() {
    const int c = blockIdx.x;
    const int d = blockIdx.y * blockDim.x + threadIdx.x;
    const int b = blockIdx.z;

    __shared__ ulonglong2 bts[LC][4];   // 16 floats = 4 ulonglong2 per step
    {
        const ulonglong2* src = reinterpret_cast<const ulonglong2*>(
            g_bt + ((size_t)b * SEQ + (size_t)c * LC) * DSTATE);
        for (int i = threadIdx.x; i < LC * 4; i += blockDim.x)
            bts[i >> 2][i & 3] = src[i];
    }
    __syncthreads();

    ull a2[8], h2[8];
    {
        const ulonglong2* ap = reinterpret_cast<const ulonglong2*>(g_abar + d * DSTATE);
#pragma unroll
        for (int j = 0; j < 4; j++) {
            ulonglong2 av = ap[j];
            a2[2*j+0] = av.x; a2[2*j+1] = av.y;
        }
    }
#pragma unroll
    for (int k = 0; k < 8; k++) h2[k] = 0ull;

#pragma unroll 4
    for (int l = 0; l < LC; l++) {
#pragma unroll
        for (int j = 0; j < 4; j++) {
            ulonglong2 bv = bts[l][j];
            h2[2*j+0] = fma2(a2[2*j+0], h2[2*j+0], bv.x);
            h2[2*j+1] = fma2(a2[2*j+1], h2[2*j+1], bv.y);
        }
    }

    ulonglong2* out = reinterpret_cast<ulonglong2*>(
        g_hstate + (((size_t)b * NC + c) * DMODEL + d) * DSTATE);
#pragma unroll
    for (int j = 0; j < 4; j++)
        out[j] = make_ulonglong2(h2[2*j], h2[2*j+1]);
}

// ---------------------------------------------------------------------------
// K3: cross-chunk combine, 2-level. Block = 256 = 64 ds x 4 chunk-groups.
// ---------------------------------------------------------------------------
__global__ void k3_combine() {
    const int ds_local = threadIdx.x & 63;
    const int cg = threadIdx.x >> 6;          // 0..3
    const int ds = blockIdx.x * 64 + ds_local;
    const int b = blockIdx.y;

    const float aL = g_aL[ds];
    float aL16 = aL;                          // aL^NCG, NCG=16 -> 4 squarings
    aL16 = aL16 * aL16; aL16 = aL16 * aL16; aL16 = aL16 * aL16; aL16 = aL16 * aL16;

    const size_t stride = (size_t)DMODEL * DSTATE;
    const float* __restrict__ src =
        g_hstate + (size_t)b * NC * stride + (size_t)cg * NCG * stride + ds;
    float* __restrict__ dst =
        g_hentry + (size_t)b * NC * stride + (size_t)cg * NCG * stride + ds;

    float e[NCG];
#pragma unroll
    for (int k = 0; k < NCG; k++) e[k] = src[(size_t)k * stride];

    float G = 0.f;
#pragma unroll
    for (int k = 0; k < NCG; k++) G = fmaf(aL, G, e[k]);

    __shared__ float GE[CG][64];
    GE[cg][ds_local] = G;
    __syncthreads();

    float E = 0.f;
#pragma unroll
    for (int g = 0; g < CG - 1; g++)
        if (g < cg) E = fmaf(aL16, E, GE[g][ds_local]);

    float H = E;
#pragma unroll
    for (int k = 0; k < NCG; k++) {
        dst[(size_t)k * stride] = H;
        H = fmaf(aL, H, e[k]);
    }
}

// ---------------------------------------------------------------------------
// K4: final scan + output, state-split across thread pairs.
// grid=(NC, DMODEL/64, BATCH), block=128. Thread pair (2i,2i+1) owns one
// d-channel; each thread carries 8 of the 16 states (h/a/cw = 12 u64 regs).
// Per-step partial sums combined via shfl_xor(1); even lane stores y.
// ---------------------------------------------------------------------------
__global__ void __launch_bounds__(128)
k4_output(const float* __restrict__ x,
          const float* __restrict__ Cw,
          const float* __restrict__ Dv,
          float* __restrict__ y) {
    const int c = blockIdx.x;
    const int dl = threadIdx.x >> 1;          // local d: 0..63
    const int sh = threadIdx.x & 1;           // state half: 0 or 1
    const int d = blockIdx.y * 64 + dl;
    const int b = blockIdx.z;

    __shared__ float sx[LC * 64];             // x tile: 8KB
    __shared__ ulonglong2 bts[LC][4];         // B_t tile: 2KB

    const size_t base = ((size_t)b * SEQ + (size_t)c * LC) * DMODEL + blockIdx.y * 64;

    // async-stage x tile: 512 float4 = 4 per thread
    {
        unsigned int sx_addr = (unsigned int)__cvta_generic_to_shared(sx);
        const float* xg = x + base;
#pragma unroll
        for (int k = 0; k < 4; k++) {
            int i = threadIdx.x + 128 * k;    // float4 index 0..511
            int l = i >> 4;                   // 16 float4 per row
            int d4 = i & 15;
            cp_async16(sx_addr + i * 16, xg + (size_t)l * DMODEL + d4 * 4);
        }
    }
    // async-stage B_t tile: 128 float4 = 1 per thread
    {
        unsigned int bt_addr = (unsigned int)__cvta_generic_to_shared(&bts[0][0]);
        const float* btg = g_bt + ((size_t)b * SEQ + (size_t)c * LC) * DSTATE;
        cp_async16(bt_addr + threadIdx.x * 16, btg + threadIdx.x * 4);
    }
    cp_async_commit();

    // per-thread register loads: this thread's 8 states (half sh)
    ull a2[4], h2[4], cw2[4];
    {
        const ulonglong2* hin = reinterpret_cast<const ulonglong2*>(
            g_hentry + (((size_t)b * NC + c) * DMODEL + d) * DSTATE) + sh * 2;
        const ulonglong2* cwp = reinterpret_cast<const ulonglong2*>(
            Cw + (size_t)d * DSTATE) + sh * 2;
        const ulonglong2* ap = reinterpret_cast<const ulonglong2*>(
            g_abar + d * DSTATE) + sh * 2;
#pragma unroll
        for (int j = 0; j < 2; j++) {
            ulonglong2 hv = hin[j];  h2[2*j] = hv.x;  h2[2*j+1] = hv.y;
            ulonglong2 cv = cwp[j];  cw2[2*j] = cv.x; cw2[2*j+1] = cv.y;
            ulonglong2 av = ap[j];   a2[2*j] = av.x;  a2[2*j+1] = av.y;
        }
    }
    const float dv = Dv[d];

    cp_async_wait0();
    __syncthreads();

    const size_t ybase = base + dl;

#pragma unroll
    for (int l = 0; l < LC; l++) {
        ull accA = 0ull, accB = 0ull;
#pragma unroll
        for (int j = 0; j < 2; j++) {
            ulonglong2 bv = bts[l][sh * 2 + j];
            h2[2*j+0] = fma2(a2[2*j+0], h2[2*j+0], bv.x);
            h2[2*j+1] = fma2(a2[2*j+1], h2[2*j+1], bv.y);
            accA = fma2(cw2[2*j+0], h2[2*j+0], accA);
            accB = fma2(cw2[2*j+1], h2[2*j+1], accB);
        }
        float2 ua = unpack2(accA);
        float2 ub = unpack2(accB);
        float part = (ua.x + ua.y) + (ub.x + ub.y);
        part += __shfl_xor_sync(0xffffffffu, part, 1);
        if (sh == 0) {
            float xval = sx[l * 64 + dl];
            y[ybase + (size_t)l * DMODEL] = fmaf(dv, xval, part);
        }
    }
}

// ---------------------------------------------------------------------------
extern "C" void kernel_launch(void* const* d_in, const int* in_sizes, int n_in,
                              void* d_out, int out_size) {
    const float* x    = (const float*)d_in[0];   // (B, L, D)
    const float* logA = (const float*)d_in[1];   // (D, S)
    const float* Bw   = (const float*)d_in[2];   // (S, D)
    const float* Cw   = (const float*)d_in[3];   // (D, S)
    const float* Dv   = (const float*)d_in[4];   // (D,)
    float* y = (float*)d_out;                    // (B, L, D)

    // K1 (+ fused K0 precompute in trailing blocks)
    k1_bproj<<<K1_BLOCKS + K0_BLOCKS, 256>>>(x, Bw, logA);

    {
        dim3 grid(NC, DMODEL / 128, BATCH);
        k2_localscan<<<grid, 128>>>();
    }
    {
        dim3 grid(DMODEL * DSTATE / 64, BATCH);
        k3_combine<<<grid, 256>>>();
    }
    {
        dim3 grid(NC, DMODEL / 64, BATCH);
        k4_output<<<grid, 128>>>(x, Cw, Dv, y);
    }
}